// round 11
// baseline (speedup 1.0000x reference)
#include <cuda_runtime.h>
#include <cuda_bf16.h>
#include <cstdint>

#define BATCH 4
#define CH    128
#define CIN   256
#define HH    224
#define WW    224
#define HW    50176
#define NCLS  41

// ---------------------------------------------------------------------------
// scratch (static device globals; no allocs)
// ---------------------------------------------------------------------------
static __device__ uint32_t g_xpack[(size_t)BATCH * CIN * HW];  // (hi|lo) bf16 pairs of concat(add,mul)
static __device__ float    g_fuse[(size_t)BATCH * CH * HW];    // conv output fp32
static __device__ uint4    g_bt4[72 * 1024];                   // 72 chunks x 16KB SW128 images (hi|lo rows)
static __device__ float    g_sum_d[BATCH * NCLS * CH];
static __device__ float    g_sum_f[BATCH * NCLS * CH];
static __device__ float    g_cnt[BATCH * NCLS];
static __device__ float    g_scale[2 * BATCH * CH];

__device__ __forceinline__ float sigmoid_fast(float x) { return 1.f / (1.f + __expf(-x)); }

__device__ __forceinline__ uint32_t pack_bf(float x) {
    __nv_bfloat16 h = __float2bfloat16(x);
    float r = x - __bfloat162float(h);
    __nv_bfloat16 l = __float2bfloat16(r);
    return (uint32_t)__bfloat16_as_ushort(h) | ((uint32_t)__bfloat16_as_ushort(l) << 16);
}

__device__ __forceinline__ uint32_t smem_u32(const void* p) {
    uint32_t a;
    asm("{ .reg .u64 t; cvta.to.shared.u64 t, %1; cvt.u32.u64 %0, t; }" : "=r"(a) : "l"(p));
    return a;
}

__device__ __forceinline__ void ldsm4(uint32_t* r, uint32_t addr) {
    asm volatile("ldmatrix.sync.aligned.m8n8.x4.shared.b16 {%0,%1,%2,%3}, [%4];"
                 : "=r"(r[0]), "=r"(r[1]), "=r"(r[2]), "=r"(r[3]) : "r"(addr));
}

__device__ __forceinline__ void mma16816(float* c, const uint32_t* a, const uint32_t* b) {
    asm volatile(
        "mma.sync.aligned.m16n8k16.row.col.f32.bf16.bf16.f32 "
        "{%0,%1,%2,%3}, {%4,%5,%6,%7}, {%8,%9}, {%0,%1,%2,%3};"
        : "+f"(c[0]), "+f"(c[1]), "+f"(c[2]), "+f"(c[3])
        : "r"(a[0]), "r"(a[1]), "r"(a[2]), "r"(a[3]), "r"(b[0]), "r"(b[1]));
}

#define CP_ASYNC16(dst, src) \
    asm volatile("cp.async.cg.shared.global [%0], [%1], 16;" :: "r"(dst), "l"(src) : "memory")
#define CP_COMMIT() asm volatile("cp.async.commit_group;" ::: "memory")
#define CP_WAIT0()  asm volatile("cp.async.wait_group 0;" ::: "memory")

// ---------------- zero accumulators ----------------
__global__ void zero_kernel() {
    int i = blockIdx.x * 256 + threadIdx.x;
    if (i < BATCH * NCLS * CH) { g_sum_d[i] = 0.f; g_sum_f[i] = 0.f; }
    if (i < BATCH * NCLS) g_cnt[i] = 0.f;
}

// ---------------- weight prepack: 72 SW128 images, rows = [hi 32ch | lo 32ch] ----------------
__global__ void wprep_kernel(const float* __restrict__ w) {
    int idx = blockIdx.x * 256 + threadIdx.x;
    if (idx >= 72 * CH * 64) return;          // 64 = 32 kk * 2 versions
    int kk = idx & 31;
    int v  = (idx >> 5) & 1;
    int oc = (idx >> 6) & 127;
    int t  = idx >> 13;          // 0..71 : tap f = t>>3, ci-block = t&7
    int f  = t >> 3;
    int ci = (t & 7) * 32 + kk;
    float wv = w[(size_t)(oc * CIN + ci) * 9 + f];
    __nv_bfloat16 hi = __float2bfloat16(wv);
    __nv_bfloat16 val = (v == 0) ? hi : __float2bfloat16(wv - __bfloat162float(hi));
    uint32_t off = ((uint32_t)oc << 7)
                 + (((uint32_t)(v * 64 + kk * 2)) ^ (((uint32_t)(oc & 7)) << 4));
    *(__nv_bfloat16*)((char*)g_bt4 + (size_t)t * 16384 + off) = val;
}

// ---------------- prep + RA(d) fused ----------------
__global__ void prep_ra_kernel(const float* __restrict__ r, const float* __restrict__ dd,
                               const int* __restrict__ label) {
    __shared__ float bins[NCLS * 33];
    __shared__ float cnts[NCLS];
    __shared__ int   slab[1024];

    const int b   = blockIdx.y;
    const int c0  = blockIdx.z * 32;
    const int p0  = blockIdx.x * 1024;
    const int tid = threadIdx.x;

    for (int i = tid; i < NCLS * 33; i += 256) bins[i] = 0.f;
    if (tid < NCLS) cnts[tid] = 0.f;
    for (int i = tid; i < 1024; i += 256) {
        int p = p0 + i;
        int y = p / WW;
        int x = p - y * WW;
        slab[i] = label[(size_t)b * 896 * 896 + (size_t)(4 * y) * 896 + 4 * x];
    }
    __syncthreads();

    if (blockIdx.z == 0) {
        for (int i = tid; i < 1024; i += 256) atomicAdd(&cnts[slab[i]], 1.f);
    }

    const int i4 = tid * 4;
    const int l0 = slab[i4], l1 = slab[i4 + 1], l2 = slab[i4 + 2], l3 = slab[i4 + 3];
    uint32_t* xb = g_xpack + (size_t)b * CIN * HW;

    for (int c = 0; c < 32; c++) {
        size_t off = ((size_t)(b * CH + c0 + c)) * HW + p0 + i4;
        float4 rv = *reinterpret_cast<const float4*>(r + off);
        float4 dv = *reinterpret_cast<const float4*>(dd + off);

        atomicAdd(&bins[l0 * 33 + c], dv.x);
        atomicAdd(&bins[l1 * 33 + c], dv.y);
        atomicAdd(&bins[l2 * 33 + c], dv.z);
        atomicAdd(&bins[l3 * 33 + c], dv.w);

        uint4 ap, mp;
        ap.x = pack_bf(rv.x + dv.x);
        ap.y = pack_bf(rv.y + dv.y);
        ap.z = pack_bf(rv.z + dv.z);
        ap.w = pack_bf(rv.w + dv.w);
        mp.x = pack_bf(rv.x * sigmoid_fast(dv.x));
        mp.y = pack_bf(rv.y * sigmoid_fast(dv.y));
        mp.z = pack_bf(rv.z * sigmoid_fast(dv.z));
        mp.w = pack_bf(rv.w * sigmoid_fast(dv.w));
        *reinterpret_cast<uint4*>(xb + ((size_t)(c0 + c)) * HW + p0 + i4)      = ap;
        *reinterpret_cast<uint4*>(xb + ((size_t)(CH + c0 + c)) * HW + p0 + i4) = mp;
    }
    __syncthreads();

    for (int i = tid; i < NCLS * 32; i += 256) {
        int k = i >> 5;
        int c = i & 31;
        atomicAdd(&g_sum_d[((size_t)b * NCLS + k) * CH + c0 + c], bins[k * 33 + c]);
    }
    if (blockIdx.z == 0 && tid < NCLS) atomicAdd(&g_cnt[b * NCLS + tid], cnts[tid]);
}

// ---------------- RA finalize ----------------
__global__ void ra_finalize_kernel(const float* __restrict__ w1_d, const float* __restrict__ w2_d,
                                   const float* __restrict__ w1_f, const float* __restrict__ w2_f) {
    const int which = blockIdx.x & 1;
    const int b     = blockIdx.x >> 1;
    const float* sums = which ? g_sum_f : g_sum_d;
    const float* w1   = which ? w1_f : w1_d;
    const float* w2   = which ? w2_f : w2_d;

    __shared__ float att[CH];
    __shared__ float hid[8];
    const int c = threadIdx.x;  // 128 threads

    float s1 = 0.f, s2 = 0.f;
    for (int k = 0; k < NCLS; k++) {
        float cnt = g_cnt[b * NCLS + k];
        float m = sums[((size_t)b * NCLS + k) * CH + c] / fmaxf(cnt, 1.f);
        s1 += m;
        s2 += m * m;
    }
    float nrm = fmaxf(sqrtf(s2), 1e-12f);
    att[c] = s1 / nrm;
    __syncthreads();

    if (c < 8) {
        float h = 0.f;
        for (int j = 0; j < CH; j++) h += att[j] * w1[c * CH + j];
        hid[c] = fmaxf(h, 0.f);
    }
    __syncthreads();

    float o = 0.f;
    #pragma unroll
    for (int j = 0; j < 8; j++) o += hid[j] * w2[c * 8 + j];
    g_scale[(which * BATCH + b) * CH + c] = 1.f / (1.f + expf(-o));
}

// ---------------- conv: mma.sync bf16, 2-stage pipeline, fused RA(fuse) ----------------
// CTA: 128 pixels x 128 oc.  72 chunks = 9 taps x 8 ci-blocks of 32 channels.
// Stage (32KB): A tile 16KB (row=pixel: [hi 32ch | lo 32ch] 128B) + B tile 16KB (row=oc, same).
// MMA group ordered term-outer so same-accumulator MMAs are 4 apart (RAW-chain relief).
#define CONV_SMEM 65536

__device__ __forceinline__ void conv_pack_store(char* aRow, const uint32_t* xs,
                                                int half, uint32_t swx) {
    #pragma unroll
    for (int q = 0; q < 2; q++) {
        uint4 hp, lp;
        const uint32_t* x = xs + 8 * q;
        hp.x = (x[0] & 0xFFFFu) | (x[1] << 16);  lp.x = (x[0] >> 16) | (x[1] & 0xFFFF0000u);
        hp.y = (x[2] & 0xFFFFu) | (x[3] << 16);  lp.y = (x[2] >> 16) | (x[3] & 0xFFFF0000u);
        hp.z = (x[4] & 0xFFFFu) | (x[5] << 16);  lp.z = (x[4] >> 16) | (x[5] & 0xFFFF0000u);
        hp.w = (x[6] & 0xFFFFu) | (x[7] << 16);  lp.w = (x[6] >> 16) | (x[7] & 0xFFFF0000u);
        uint32_t co_h = ((uint32_t)(half * 32 + 16 * q)) ^ swx;
        uint32_t co_l = ((uint32_t)(64 + half * 32 + 16 * q)) ^ swx;
        *(uint4*)(aRow + co_h) = hp;
        *(uint4*)(aRow + co_l) = lp;
    }
}

__global__ __launch_bounds__(256, 2) void conv_mma_kernel(const int* __restrict__ label) {
    extern __shared__ __align__(1024) char smem[];
    const uint32_t sb = smem_u32(smem);
    const int tid  = threadIdx.x;
    const int wid  = tid >> 5;
    const int lane = tid & 31;
    const int b    = blockIdx.y;
    const int p0   = blockIdx.x * 128;

    const int wm = wid & 1;        // M warp (0..1) -> 64 pixels
    const int wn = wid >> 1;       // N warp (0..3) -> 32 oc
    const int rln  = lane & 7;
    const int quad = lane >> 3;

    const int a_row_off = rln + ((quad & 1) << 3);
    const uint32_t a_kb = (uint32_t)(quad >> 1) << 4;
    const int b_oc_off  = rln + ((quad >> 1) << 3);
    const uint32_t b_kb = (uint32_t)(quad & 1) << 4;
    const uint32_t lxor = (uint32_t)rln << 4;

    const uint32_t aBase = sb + (uint32_t)(wm * 64 + a_row_off) * 128;
    const uint32_t bBase = sb + 16384 + (uint32_t)(wn * 32 + b_oc_off) * 128;

    // loader mapping: 2 threads per pixel row, each 16 channels
    const int row  = tid >> 1;
    const int half = tid & 1;
    const int p    = p0 + row;
    const int py   = p / WW;
    const int px   = p - py * WW;
    const uint32_t swx = (uint32_t)(row & 7) << 4;

    float acc[4][4][4];
    #pragma unroll
    for (int i = 0; i < 4; i++)
        #pragma unroll
        for (int j = 0; j < 4; j++)
            #pragma unroll
            for (int k = 0; k < 4; k++) acc[i][j][k] = 0.f;

    uint32_t xs[16];

    // ---- prologue: chunk 0 -> stage 0 ----
    {
        const int iy = py - 1, ix = px - 1;
        const bool valid = ((unsigned)iy < (unsigned)HH) && ((unsigned)ix < (unsigned)WW);
        const uint32_t* sp = g_xpack + ((size_t)(b * CIN + half * 16)) * HW + (iy * WW + ix);
        #pragma unroll
        for (int e = 0; e < 16; e++) xs[e] = valid ? sp[(size_t)e * HW] : 0u;
        const char* bsrc = (const char*)g_bt4 + tid * 16;
        uint32_t bd = sb + 16384 + tid * 16;
        #pragma unroll
        for (int i = 0; i < 4; i++) CP_ASYNC16(bd + i * 4096, bsrc + i * 4096);
        CP_COMMIT();
        conv_pack_store(smem + row * 128, xs, half, swx);
    }
    CP_WAIT0();
    __syncthreads();

    for (int c = 0; c < 72; c++) {
        const int s = c & 1;

        // prefetch chunk c+1: A LDGs into regs (latency hides under MMA), B via cp.async
        if (c < 71) {
            const int cn = c + 1;
            const int f  = cn >> 3;
            const int cc = cn & 7;
            const int fy = f / 3;
            const int iy = py + fy - 1;
            const int ix = px + (f - fy * 3) - 1;
            const bool valid = ((unsigned)iy < (unsigned)HH) && ((unsigned)ix < (unsigned)WW);
            const uint32_t* sp = g_xpack + ((size_t)(b * CIN + cc * 32 + half * 16)) * HW
                                         + (iy * WW + ix);
            #pragma unroll
            for (int e = 0; e < 16; e++) xs[e] = valid ? sp[(size_t)e * HW] : 0u;

            const char* bsrc = (const char*)g_bt4 + (size_t)cn * 16384 + tid * 16;
            uint32_t bd = sb + (uint32_t)(s ^ 1) * 32768 + 16384 + tid * 16;
            #pragma unroll
            for (int i = 0; i < 4; i++) CP_ASYNC16(bd + i * 4096, bsrc + i * 4096);
            CP_COMMIT();
        }

        // ---- MMA on stage s: term-outer ordering, same-acc distance = 4 ----
        const uint32_t aB = aBase + (uint32_t)s * 32768;
        const uint32_t bB = bBase + (uint32_t)s * 32768;
        #pragma unroll
        for (int ks = 0; ks < 2; ks++) {
            const uint32_t acoH = ((uint32_t)(ks * 32) + a_kb) ^ lxor;
            const uint32_t acoL = ((uint32_t)(64 + ks * 32) + a_kb) ^ lxor;
            const uint32_t bcoH = ((uint32_t)(ks * 32) + b_kb) ^ lxor;
            const uint32_t bcoL = ((uint32_t)(64 + ks * 32) + b_kb) ^ lxor;

            uint32_t Bh[2][4], Bl[2][4];
            #pragma unroll
            for (int ng = 0; ng < 2; ng++) {
                ldsm4(Bh[ng], bB + ng * 2048 + bcoH);
                ldsm4(Bl[ng], bB + ng * 2048 + bcoL);
            }
            #pragma unroll
            for (int mf = 0; mf < 4; mf++) {
                uint32_t Ahi[4], Alo[4];
                ldsm4(Ahi, aB + mf * 2048 + acoH);
                ldsm4(Alo, aB + mf * 2048 + acoL);
                // term 1: Ahi x Bh  (touch all 4 accs)
                mma16816(acc[mf][0], Ahi, Bh[0]);
                mma16816(acc[mf][1], Ahi, Bh[0] + 2);
                mma16816(acc[mf][2], Ahi, Bh[1]);
                mma16816(acc[mf][3], Ahi, Bh[1] + 2);
                // term 2: Ahi x Bl
                mma16816(acc[mf][0], Ahi, Bl[0]);
                mma16816(acc[mf][1], Ahi, Bl[0] + 2);
                mma16816(acc[mf][2], Ahi, Bl[1]);
                mma16816(acc[mf][3], Ahi, Bl[1] + 2);
                // term 3: Alo x Bh
                mma16816(acc[mf][0], Alo, Bh[0]);
                mma16816(acc[mf][1], Alo, Bh[0] + 2);
                mma16816(acc[mf][2], Alo, Bh[1]);
                mma16816(acc[mf][3], Alo, Bh[1] + 2);
            }
        }

        // store prefetched A into stage s^1
        if (c < 71) {
            conv_pack_store(smem + (size_t)(s ^ 1) * 32768 + row * 128, xs, half, swx);
        }
        CP_WAIT0();
        __syncthreads();
    }

    // ---- fused epilogue: write g_fuse + RA(fuse) bins ----
    float* bins = (float*)smem;                    // 41*129 floats = 21156 B
    int*   slb  = (int*)(smem + 21248);            // 128 labels
    for (int i = tid; i < NCLS * 129; i += 256) bins[i] = 0.f;
    if (tid < 128) {
        int pp = p0 + tid;
        int yy = pp / WW;
        int xx = pp - yy * WW;
        slb[tid] = label[(size_t)b * 896 * 896 + (size_t)(4 * yy) * 896 + 4 * xx];
    }
    __syncthreads();

    float* fb = g_fuse + (size_t)b * CH * HW;
    const int prl = wm * 64 + (lane >> 2);
    const int oc0 = wn * 32 + (lane & 3) * 2;
    #pragma unroll
    for (int mf = 0; mf < 4; mf++) {
        const int px0 = prl + mf * 16;
        const int la  = slb[px0];
        const int lb2 = slb[px0 + 8];
        #pragma unroll
        for (int nf = 0; nf < 4; nf++) {
            const int oc = oc0 + nf * 8;
            float v0 = acc[mf][nf][0], v1 = acc[mf][nf][1];
            float v2 = acc[mf][nf][2], v3 = acc[mf][nf][3];
            fb[(size_t)oc * HW + p0 + px0]           = v0;
            fb[(size_t)(oc + 1) * HW + p0 + px0]     = v1;
            fb[(size_t)oc * HW + p0 + px0 + 8]       = v2;
            fb[(size_t)(oc + 1) * HW + p0 + px0 + 8] = v3;
            atomicAdd(&bins[la * 129 + oc], v0);
            atomicAdd(&bins[la * 129 + oc + 1], v1);
            atomicAdd(&bins[lb2 * 129 + oc], v2);
            atomicAdd(&bins[lb2 * 129 + oc + 1], v3);
        }
    }
    __syncthreads();
    for (int i = tid; i < NCLS * CH; i += 256) {
        int k = i >> 7;
        int c = i & 127;
        atomicAdd(&g_sum_f[((size_t)b * NCLS + k) * CH + c], bins[k * 129 + c]);
    }
}

// ---------------- final: out = fuse*scale_f + d*scale_d ----------------
__global__ void final_kernel(const float* __restrict__ dd, float* __restrict__ out) {
    int idx = blockIdx.x * 256 + threadIdx.x;
    const int n4 = BATCH * CH * HW / 4;
    if (idx >= n4) return;
    int i = idx * 4;
    int bc = i / HW;
    int b = bc >> 7;
    int c = bc & (CH - 1);
    float sd = g_scale[b * CH + c];
    float sf = g_scale[(BATCH + b) * CH + c];
    float4 dv = *reinterpret_cast<const float4*>(dd + i);
    float4 fv = *reinterpret_cast<const float4*>(g_fuse + i);
    float4 o;
    o.x = fv.x * sf + dv.x * sd;
    o.y = fv.y * sf + dv.y * sd;
    o.z = fv.z * sf + dv.z * sd;
    o.w = fv.w * sf + dv.w * sd;
    *reinterpret_cast<float4*>(out + i) = o;
}

// ---------------- launcher ----------------
extern "C" void kernel_launch(void* const* d_in, const int* in_sizes, int n_in,
                              void* d_out, int out_size) {
    const float* r      = (const float*)d_in[0];
    const float* d      = (const float*)d_in[1];
    const int*   label  = (const int*)  d_in[2];
    const float* w_fuse = (const float*)d_in[3];
    const float* w1_d   = (const float*)d_in[4];
    const float* w2_d   = (const float*)d_in[5];
    const float* w1_f   = (const float*)d_in[6];
    const float* w2_f   = (const float*)d_in[7];
    float* out = (float*)d_out;

    static int smem_set = 0;
    if (!smem_set) {
        cudaFuncSetAttribute(conv_mma_kernel, cudaFuncAttributeMaxDynamicSharedMemorySize, CONV_SMEM);
        smem_set = 1;
    }

    const int n4 = BATCH * CH * HW / 4;

    zero_kernel<<<(BATCH * NCLS * CH + 255) / 256, 256>>>();                       // 1
    wprep_kernel<<<(72 * CH * 64 + 255) / 256, 256>>>(w_fuse);                     // 2
    prep_ra_kernel<<<dim3(HW / 1024, BATCH, 4), 256>>>(r, d, label);               // 3
    conv_mma_kernel<<<dim3(HW / 128, BATCH), 256, CONV_SMEM>>>(label);             // 4
    ra_finalize_kernel<<<2 * BATCH, CH>>>(w1_d, w2_d, w1_f, w2_f);                 // 5
    final_kernel<<<(n4 + 255) / 256, 256>>>(d, out);                               // 6
}

// round 13
// speedup vs baseline: 1.8967x; 1.8967x over previous
#include <cuda_runtime.h>
#include <cuda_fp16.h>
#include <cstdint>

#define BATCH 4
#define CH    128
#define CIN   256
#define HH    224
#define WW    224
#define HW    50176
#define NCLS  41

// ---------------------------------------------------------------------------
// scratch (static device globals; no allocs)
// ---------------------------------------------------------------------------
// g_xh2: fp16 channel-PAIR packed: word = (fp16 x[2cp], fp16 x[2cp+1]) for one pixel.
// cp in [0,64) = add-plane pairs, [64,128) = mul-plane pairs.
static __device__ uint32_t g_xh2[(size_t)BATCH * 128 * HW];
static __device__ float    g_fuse[(size_t)BATCH * CH * HW];    // conv output fp32
static __device__ uint4    g_bt4[36 * 1024];                   // 36 chunks x 16KB SW128 fp16 B images
static __device__ float    g_sum_d[BATCH * NCLS * CH];
static __device__ float    g_sum_f[BATCH * NCLS * CH];
static __device__ float    g_cnt[BATCH * NCLS];
static __device__ float    g_scale[2 * BATCH * CH];

__device__ __forceinline__ float sigmoid_fast(float x) { return 1.f / (1.f + __expf(-x)); }

__device__ __forceinline__ uint32_t smem_u32(const void* p) {
    uint32_t a;
    asm("{ .reg .u64 t; cvta.to.shared.u64 t, %1; cvt.u32.u64 %0, t; }" : "=r"(a) : "l"(p));
    return a;
}

__device__ __forceinline__ void ldsm4(uint32_t* r, uint32_t addr) {
    asm volatile("ldmatrix.sync.aligned.m8n8.x4.shared.b16 {%0,%1,%2,%3}, [%4];"
                 : "=r"(r[0]), "=r"(r[1]), "=r"(r[2]), "=r"(r[3]) : "r"(addr));
}

__device__ __forceinline__ void mma16816(float* c, const uint32_t* a, const uint32_t* b) {
    asm volatile(
        "mma.sync.aligned.m16n8k16.row.col.f32.f16.f16.f32 "
        "{%0,%1,%2,%3}, {%4,%5,%6,%7}, {%8,%9}, {%0,%1,%2,%3};"
        : "+f"(c[0]), "+f"(c[1]), "+f"(c[2]), "+f"(c[3])
        : "r"(a[0]), "r"(a[1]), "r"(a[2]), "r"(a[3]), "r"(b[0]), "r"(b[1]));
}

#define CP_ASYNC16(dst, src) \
    asm volatile("cp.async.cg.shared.global [%0], [%1], 16;" :: "r"(dst), "l"(src) : "memory")
#define CP_COMMIT() asm volatile("cp.async.commit_group;" ::: "memory")
#define CP_WAIT0()  asm volatile("cp.async.wait_group 0;" ::: "memory")

__device__ __forceinline__ uint32_t h2pack(float a, float b) {
    __half2 h = __floats2half2_rn(a, b);
    return *reinterpret_cast<uint32_t*>(&h);
}

// ---------------- zero accumulators ----------------
__global__ void zero_kernel() {
    int i = blockIdx.x * 256 + threadIdx.x;
    if (i < BATCH * NCLS * CH) { g_sum_d[i] = 0.f; g_sum_f[i] = 0.f; }
    if (i < BATCH * NCLS) g_cnt[i] = 0.f;
}

// ---------------- weight prepack: 36 SW128 fp16 images (128 oc x 64 ch) ----------------
__global__ void wprep_kernel(const float* __restrict__ w) {
    int idx = blockIdx.x * 256 + threadIdx.x;
    if (idx >= 36 * CH * 64) return;
    int kk = idx & 63;
    int oc = (idx >> 6) & 127;
    int t  = idx >> 13;          // 0..35 : tap f = t>>2, ci-block = t&3
    int f  = t >> 2;
    int ci = (t & 3) * 64 + kk;
    float wv = w[(size_t)(oc * CIN + ci) * 9 + f];
    uint32_t off = ((uint32_t)oc << 7) + (((uint32_t)kk * 2) ^ (((uint32_t)(oc & 7)) << 4));
    *(__half*)((char*)g_bt4 + (size_t)t * 16384 + off) = __float2half(wv);
}

// ---------------- prep + RA(d) fused ----------------
// grid (HW/1024, BATCH, 4); block 256. Each block: 1024 pixels x 32 channels.
__global__ void prep_ra_kernel(const float* __restrict__ r, const float* __restrict__ dd,
                               const int* __restrict__ label) {
    __shared__ float bins[NCLS * 33];
    __shared__ float cnts[NCLS];
    __shared__ int   slab[1024];

    const int b   = blockIdx.y;
    const int c0  = blockIdx.z * 32;
    const int p0  = blockIdx.x * 1024;
    const int tid = threadIdx.x;

    for (int i = tid; i < NCLS * 33; i += 256) bins[i] = 0.f;
    if (tid < NCLS) cnts[tid] = 0.f;
    for (int i = tid; i < 1024; i += 256) {
        int p = p0 + i;
        int y = p / WW;
        int x = p - y * WW;
        slab[i] = label[(size_t)b * 896 * 896 + (size_t)(4 * y) * 896 + 4 * x];
    }
    __syncthreads();

    if (blockIdx.z == 0) {
        for (int i = tid; i < 1024; i += 256) atomicAdd(&cnts[slab[i]], 1.f);
    }

    const int i4 = tid * 4;
    const int l0 = slab[i4], l1 = slab[i4 + 1], l2 = slab[i4 + 2], l3 = slab[i4 + 3];
    uint32_t* xb = g_xh2 + (size_t)b * 128 * HW;

    for (int c = 0; c < 32; c += 2) {
        size_t off0 = ((size_t)(b * CH + c0 + c)) * HW + p0 + i4;
        float4 rv0 = *reinterpret_cast<const float4*>(r + off0);
        float4 dv0 = *reinterpret_cast<const float4*>(dd + off0);
        float4 rv1 = *reinterpret_cast<const float4*>(r + off0 + HW);
        float4 dv1 = *reinterpret_cast<const float4*>(dd + off0 + HW);

        atomicAdd(&bins[l0 * 33 + c], dv0.x);
        atomicAdd(&bins[l1 * 33 + c], dv0.y);
        atomicAdd(&bins[l2 * 33 + c], dv0.z);
        atomicAdd(&bins[l3 * 33 + c], dv0.w);
        atomicAdd(&bins[l0 * 33 + c + 1], dv1.x);
        atomicAdd(&bins[l1 * 33 + c + 1], dv1.y);
        atomicAdd(&bins[l2 * 33 + c + 1], dv1.z);
        atomicAdd(&bins[l3 * 33 + c + 1], dv1.w);

        uint4 ap, mp;
        ap.x = h2pack(rv0.x + dv0.x, rv1.x + dv1.x);
        ap.y = h2pack(rv0.y + dv0.y, rv1.y + dv1.y);
        ap.z = h2pack(rv0.z + dv0.z, rv1.z + dv1.z);
        ap.w = h2pack(rv0.w + dv0.w, rv1.w + dv1.w);
        mp.x = h2pack(rv0.x * sigmoid_fast(dv0.x), rv1.x * sigmoid_fast(dv1.x));
        mp.y = h2pack(rv0.y * sigmoid_fast(dv0.y), rv1.y * sigmoid_fast(dv1.y));
        mp.z = h2pack(rv0.z * sigmoid_fast(dv0.z), rv1.z * sigmoid_fast(dv1.z));
        mp.w = h2pack(rv0.w * sigmoid_fast(dv0.w), rv1.w * sigmoid_fast(dv1.w));

        const int cp = (c0 + c) >> 1;      // pair index within add plane
        *reinterpret_cast<uint4*>(xb + ((size_t)cp) * HW + p0 + i4)        = ap;
        *reinterpret_cast<uint4*>(xb + ((size_t)(64 + cp)) * HW + p0 + i4) = mp;
    }
    __syncthreads();

    for (int i = tid; i < NCLS * 32; i += 256) {
        int k = i >> 5;
        int c = i & 31;
        atomicAdd(&g_sum_d[((size_t)b * NCLS + k) * CH + c0 + c], bins[k * 33 + c]);
    }
    if (blockIdx.z == 0 && tid < NCLS) atomicAdd(&g_cnt[b * NCLS + tid], cnts[tid]);
}

// ---------------- RA finalize ----------------
__global__ void ra_finalize_kernel(const float* __restrict__ w1_d, const float* __restrict__ w2_d,
                                   const float* __restrict__ w1_f, const float* __restrict__ w2_f) {
    const int which = blockIdx.x & 1;
    const int b     = blockIdx.x >> 1;
    const float* sums = which ? g_sum_f : g_sum_d;
    const float* w1   = which ? w1_f : w1_d;
    const float* w2   = which ? w2_f : w2_d;

    __shared__ float att[CH];
    __shared__ float hid[8];
    const int c = threadIdx.x;  // 128 threads

    float s1 = 0.f, s2 = 0.f;
    for (int k = 0; k < NCLS; k++) {
        float cnt = g_cnt[b * NCLS + k];
        float m = sums[((size_t)b * NCLS + k) * CH + c] / fmaxf(cnt, 1.f);
        s1 += m;
        s2 += m * m;
    }
    float nrm = fmaxf(sqrtf(s2), 1e-12f);
    att[c] = s1 / nrm;
    __syncthreads();

    if (c < 8) {
        float h = 0.f;
        for (int j = 0; j < CH; j++) h += att[j] * w1[c * CH + j];
        hid[c] = fmaxf(h, 0.f);
    }
    __syncthreads();

    float o = 0.f;
    #pragma unroll
    for (int j = 0; j < 8; j++) o += hid[j] * w2[c * 8 + j];
    g_scale[(which * BATCH + b) * CH + c] = 1.f / (1.f + expf(-o));
}

// ---------------- conv: mma.sync fp16 single-term, 2-stage pipeline, fused RA(fuse) ----------------
// CTA: 128 pixels x 128 oc.  36 chunks = 9 taps x 4 ci-blocks of 64 channels.
// Stage (32KB): A tile 16KB (128 px rows x 64 fp16 ch, SW128) + B tile 16KB (128 oc x 64 ch).
// 2 stages = 64KB.  Prefetch chunk c+1 (A LDGs in regs, B cp.async) overlaps MMA of chunk c.
#define CONV_SMEM 65536

__device__ __forceinline__ void conv_store_a(char* aRow, const uint32_t* xs,
                                             int half, uint32_t swx) {
    #pragma unroll
    for (int q = 0; q < 4; q++) {
        uint4 v;
        v.x = xs[4 * q];  v.y = xs[4 * q + 1];  v.z = xs[4 * q + 2];  v.w = xs[4 * q + 3];
        uint32_t co = ((uint32_t)(half * 64 + 16 * q)) ^ swx;
        *(uint4*)(aRow + co) = v;
    }
}

__global__ __launch_bounds__(256, 2) void conv_mma_kernel(const int* __restrict__ label) {
    extern __shared__ __align__(1024) char smem[];
    const uint32_t sb = smem_u32(smem);
    const int tid  = threadIdx.x;
    const int wid  = tid >> 5;
    const int lane = tid & 31;
    const int b    = blockIdx.y;
    const int p0   = blockIdx.x * 128;

    const int wm = wid & 1;        // M warp (0..1) -> 64 pixels
    const int wn = wid >> 1;       // N warp (0..3) -> 32 oc
    const int rln  = lane & 7;
    const int quad = lane >> 3;

    const int a_row_off = rln + ((quad & 1) << 3);
    const uint32_t a_kb = (uint32_t)(quad >> 1) << 4;
    const int b_oc_off  = rln + ((quad >> 1) << 3);
    const uint32_t b_kb = (uint32_t)(quad & 1) << 4;
    const uint32_t lxor = (uint32_t)rln << 4;

    const uint32_t aBase = sb + (uint32_t)(wm * 64 + a_row_off) * 128;
    const uint32_t bBase = sb + 16384 + (uint32_t)(wn * 32 + b_oc_off) * 128;

    // loader mapping: 2 threads per pixel row, each 16 channel-pairs (32 ch)
    const int row  = tid >> 1;
    const int half = tid & 1;
    const int p    = p0 + row;
    const int py   = p / WW;
    const int px   = p - py * WW;
    const uint32_t swx = (uint32_t)(row & 7) << 4;

    float acc[4][4][4];
    #pragma unroll
    for (int i = 0; i < 4; i++)
        #pragma unroll
        for (int j = 0; j < 4; j++)
            #pragma unroll
            for (int k = 0; k < 4; k++) acc[i][j][k] = 0.f;

    uint32_t xs[16];

    // ---- prologue: chunk 0 -> stage 0 ----
    {
        const int iy = py - 1, ix = px - 1;
        const bool valid = ((unsigned)iy < (unsigned)HH) && ((unsigned)ix < (unsigned)WW);
        const uint32_t* sp = g_xh2 + ((size_t)(b * 128 + half * 16)) * HW + (iy * WW + ix);
        #pragma unroll
        for (int e = 0; e < 16; e++) xs[e] = valid ? sp[(size_t)e * HW] : 0u;
        const char* bsrc = (const char*)g_bt4 + tid * 16;
        uint32_t bd = sb + 16384 + tid * 16;
        #pragma unroll
        for (int i = 0; i < 4; i++) CP_ASYNC16(bd + i * 4096, bsrc + i * 4096);
        CP_COMMIT();
        conv_store_a(smem + row * 128, xs, half, swx);
    }
    CP_WAIT0();
    __syncthreads();

    for (int c = 0; c < 36; c++) {
        const int s = c & 1;

        // prefetch chunk c+1: A LDGs into regs (latency hides under MMA), B via cp.async
        if (c < 35) {
            const int cn = c + 1;
            const int f  = cn >> 2;
            const int cc = cn & 3;
            const int fy = f / 3;
            const int iy = py + fy - 1;
            const int ix = px + (f - fy * 3) - 1;
            const bool valid = ((unsigned)iy < (unsigned)HH) && ((unsigned)ix < (unsigned)WW);
            const uint32_t* sp = g_xh2 + ((size_t)(b * 128 + cc * 32 + half * 16)) * HW
                                       + (iy * WW + ix);
            #pragma unroll
            for (int e = 0; e < 16; e++) xs[e] = valid ? sp[(size_t)e * HW] : 0u;

            const char* bsrc = (const char*)g_bt4 + (size_t)cn * 16384 + tid * 16;
            uint32_t bd = sb + (uint32_t)(s ^ 1) * 32768 + 16384 + tid * 16;
            #pragma unroll
            for (int i = 0; i < 4; i++) CP_ASYNC16(bd + i * 4096, bsrc + i * 4096);
            CP_COMMIT();
        }

        // ---- MMA on stage s: K = 64 ch = 4 k16 steps, single fp16 term ----
        const uint32_t aB = aBase + (uint32_t)s * 32768;
        const uint32_t bB = bBase + (uint32_t)s * 32768;
        #pragma unroll
        for (int ks = 0; ks < 4; ks++) {
            const uint32_t aco = ((uint32_t)(ks * 32) + a_kb) ^ lxor;
            const uint32_t bco = ((uint32_t)(ks * 32) + b_kb) ^ lxor;

            uint32_t Bf[2][4];
            ldsm4(Bf[0], bB + bco);
            ldsm4(Bf[1], bB + 2048 + bco);
            #pragma unroll
            for (int mf = 0; mf < 4; mf++) {
                uint32_t Af[4];
                ldsm4(Af, aB + mf * 2048 + aco);
                mma16816(acc[mf][0], Af, Bf[0]);
                mma16816(acc[mf][1], Af, Bf[0] + 2);
                mma16816(acc[mf][2], Af, Bf[1]);
                mma16816(acc[mf][3], Af, Bf[1] + 2);
            }
        }

        // store prefetched A into stage s^1
        if (c < 35) {
            conv_store_a(smem + (size_t)(s ^ 1) * 32768 + row * 128, xs, half, swx);
        }
        CP_WAIT0();
        __syncthreads();
    }

    // ---- fused epilogue: write g_fuse + RA(fuse) bins ----
    float* bins = (float*)smem;                    // 41*129 floats = 21156 B
    int*   slb  = (int*)(smem + 21248);            // 128 labels
    for (int i = tid; i < NCLS * 129; i += 256) bins[i] = 0.f;
    if (tid < 128) {
        int pp = p0 + tid;
        int yy = pp / WW;
        int xx = pp - yy * WW;
        slb[tid] = label[(size_t)b * 896 * 896 + (size_t)(4 * yy) * 896 + 4 * xx];
    }
    __syncthreads();

    float* fb = g_fuse + (size_t)b * CH * HW;
    const int prl = wm * 64 + (lane >> 2);
    const int oc0 = wn * 32 + (lane & 3) * 2;
    #pragma unroll
    for (int mf = 0; mf < 4; mf++) {
        const int px0 = prl + mf * 16;
        const int la  = slb[px0];
        const int lb2 = slb[px0 + 8];
        #pragma unroll
        for (int nf = 0; nf < 4; nf++) {
            const int oc = oc0 + nf * 8;
            float v0 = acc[mf][nf][0], v1 = acc[mf][nf][1];
            float v2 = acc[mf][nf][2], v3 = acc[mf][nf][3];
            fb[(size_t)oc * HW + p0 + px0]           = v0;
            fb[(size_t)(oc + 1) * HW + p0 + px0]     = v1;
            fb[(size_t)oc * HW + p0 + px0 + 8]       = v2;
            fb[(size_t)(oc + 1) * HW + p0 + px0 + 8] = v3;
            atomicAdd(&bins[la * 129 + oc], v0);
            atomicAdd(&bins[la * 129 + oc + 1], v1);
            atomicAdd(&bins[lb2 * 129 + oc], v2);
            atomicAdd(&bins[lb2 * 129 + oc + 1], v3);
        }
    }
    __syncthreads();
    for (int i = tid; i < NCLS * CH; i += 256) {
        int k = i >> 7;
        int c = i & 127;
        atomicAdd(&g_sum_f[((size_t)b * NCLS + k) * CH + c], bins[k * 129 + c]);
    }
}

// ---------------- final: out = fuse*scale_f + d*scale_d ----------------
__global__ void final_kernel(const float* __restrict__ dd, float* __restrict__ out) {
    int idx = blockIdx.x * 256 + threadIdx.x;
    const int n4 = BATCH * CH * HW / 4;
    if (idx >= n4) return;
    int i = idx * 4;
    int bc = i / HW;
    int b = bc >> 7;
    int c = bc & (CH - 1);
    float sd = g_scale[b * CH + c];
    float sf = g_scale[(BATCH + b) * CH + c];
    float4 dv = *reinterpret_cast<const float4*>(dd + i);
    float4 fv = *reinterpret_cast<const float4*>(g_fuse + i);
    float4 o;
    o.x = fv.x * sf + dv.x * sd;
    o.y = fv.y * sf + dv.y * sd;
    o.z = fv.z * sf + dv.z * sd;
    o.w = fv.w * sf + dv.w * sd;
    *reinterpret_cast<float4*>(out + i) = o;
}

// ---------------- launcher ----------------
extern "C" void kernel_launch(void* const* d_in, const int* in_sizes, int n_in,
                              void* d_out, int out_size) {
    const float* r      = (const float*)d_in[0];
    const float* d      = (const float*)d_in[1];
    const int*   label  = (const int*)  d_in[2];
    const float* w_fuse = (const float*)d_in[3];
    const float* w1_d   = (const float*)d_in[4];
    const float* w2_d   = (const float*)d_in[5];
    const float* w1_f   = (const float*)d_in[6];
    const float* w2_f   = (const float*)d_in[7];
    float* out = (float*)d_out;

    static int smem_set = 0;
    if (!smem_set) {
        cudaFuncSetAttribute(conv_mma_kernel, cudaFuncAttributeMaxDynamicSharedMemorySize, CONV_SMEM);
        smem_set = 1;
    }

    const int n4 = BATCH * CH * HW / 4;

    zero_kernel<<<(BATCH * NCLS * CH + 255) / 256, 256>>>();                       // 1
    wprep_kernel<<<(36 * CH * 64 + 255) / 256, 256>>>(w_fuse);                     // 2
    prep_ra_kernel<<<dim3(HW / 1024, BATCH, 4), 256>>>(r, d, label);               // 3
    conv_mma_kernel<<<dim3(HW / 128, BATCH), 256, CONV_SMEM>>>(label);             // 4
    ra_finalize_kernel<<<2 * BATCH, CH>>>(w1_d, w2_d, w1_f, w2_f);                 // 5
    final_kernel<<<(n4 + 255) / 256, 256>>>(d, out);                               // 6
}